// round 12
// baseline (speedup 1.0000x reference)
#include <cuda_runtime.h>

#define CCH   512
#define HW    49
#define CHW   (CCH * HW)     // 25088 floats per sample
#define NVEC  (CHW / 4)      // 6272 float4 per sample
#define NTHR  1024
#define EPS   1e-5f

// Stride of 1024 float4 = 4096 floats = 83*49 + 29
#define QSTEP 83
#define RSTEP 29

__device__ unsigned int g_ctr;

__global__ void reset_ctr_kernel() { g_ctr = 0u; }

__global__ __launch_bounds__(NTHR, 1)
void gate_l1_kernel(const float* __restrict__ x, float* __restrict__ out, int N) {
    __shared__ float part[NTHR];
    __shared__ float gateS[CCH + 8];   // pad keeps q+1 read in-bounds
    __shared__ float redA[32];
    __shared__ float redB[32];
    __shared__ int   s_cur;

    const int tid  = threadIdx.x;
    const int lane = tid & 31;
    const int wid  = tid >> 5;

    for (;;) {
        // ---- Dynamic sample grab (tail-balanced) ----
        if (tid == 0) s_cur = (int)atomicAdd(&g_ctr, 1u);
        __syncthreads();
        const int s = s_cur;
        if (s >= N) break;

        const float* __restrict__ xs = x + (size_t)s * CHW;

        // ---- Pass 1: per-channel partial sums straight from GMEM ----
        // Thread pair (c, c+512) splits channel c's 49 floats as 25 + 24.
        // Scalar LDGs populate L1; per-warp footprint is a contiguous ~6 KB
        // slice, so the whole sample ends up resident in L1 for pass 2.
        {
            const int c    = tid & (CCH - 1);
            const int half = tid >> 9;
            const float* row = xs + c * HW + half * 25;
            float acc = 0.0f;
            #pragma unroll
            for (int j = 0; j < 24; j++) acc += row[j];
            if (half == 0) acc += row[24];
            part[tid] = acc;
        }
        __syncthreads();

        float y = 0.0f;
        if (tid < CCH) y = (part[tid] + part[tid + CCH]) * (1.0f / 49.0f);

        // ---- Stats: block reduce sum(y), sum(y^2) over 512 lanes ----
        float a = y, b = y * y;
        #pragma unroll
        for (int off = 16; off > 0; off >>= 1) {
            a += __shfl_xor_sync(0xffffffffu, a, off);
            b += __shfl_xor_sync(0xffffffffu, b, off);
        }
        if (lane == 0) { redA[wid] = a; redB[wid] = b; }
        __syncthreads();

        // Every warp redundantly reduces the 32 partials -> stats in regs.
        a = redA[lane];
        b = redB[lane];
        #pragma unroll
        for (int off = 16; off > 0; off >>= 1) {
            a += __shfl_xor_sync(0xffffffffu, a, off);
            b += __shfl_xor_sync(0xffffffffu, b, off);
        }
        {
            const float m   = a * (1.0f / (float)CCH);
            const float mx2 = b * (1.0f / (float)CCH);
            float var = mx2 - m * m;
            var = var > 0.0f ? var : 0.0f;
            const float inv = rsqrtf(var + EPS);
            if (tid < CCH) {
                const float yn = (y - m) * inv;
                gateS[tid] = __expf(-yn * yn);   // C_PARAM=2 -> exp(-yn^2)
            }
        }
        __syncthreads();

        // ---- Pass 2: re-read as float4 (L1 hits), gate, coalesced STG ----
        {
            const float4* __restrict__ xg4 =
                reinterpret_cast<const float4*>(xs);
            float4* __restrict__ og4 =
                reinterpret_cast<float4*>(out + (size_t)s * CHW);
            int e = tid * 4;
            int q = e / HW;            // one divide per thread per sample
            int r = e - q * HW;
            #pragma unroll 2
            for (int i = tid; i < NVEC; i += NTHR) {
                float4 v = xg4[i];
                const float g0 = gateS[q];
                const float g1 = gateS[q + 1];
                v.x *= g0;
                v.y *= (r + 1 >= HW) ? g1 : g0;
                v.z *= (r + 2 >= HW) ? g1 : g0;
                v.w *= (r + 3 >= HW) ? g1 : g0;
                og4[i] = v;
                q += QSTEP; r += RSTEP;
                if (r >= HW) { r -= HW; q += 1; }
            }
        }
        // No trailing barrier: the loop-top __syncthreads orders everything
        // (part[], gateS[] of the next sample are written only after it).
    }
}

extern "C" void kernel_launch(void* const* d_in, const int* in_sizes, int n_in,
                              void* d_out, int out_size) {
    const float* x = (const float*)d_in[0];
    float* out = (float*)d_out;
    const int N = in_sizes[0] / CHW;   // 2048

    int sm_count = 0;
    if (cudaDeviceGetAttribute(&sm_count, cudaDevAttrMultiProcessorCount, 0)
        != cudaSuccess || sm_count <= 0)
        sm_count = 148;

    int grid = sm_count;               // 1 persistent CTA per SM
    if (grid > N) grid = N;

    reset_ctr_kernel<<<1, 1>>>();
    gate_l1_kernel<<<grid, NTHR>>>(x, out, N);
}

// round 13
// speedup vs baseline: 1.1661x; 1.1661x over previous
#include <cuda_runtime.h>
#include <cstdint>

#define CCH   512
#define HW    49
#define CHW   (CCH * HW)          // 25088 floats per sample
#define NVEC  (CHW / 4)           // 6272 float4 per sample
#define NTHR  1024
#define EPS   1e-5f
#define TILE_BYTES (CHW * 4)      // 100352 B

// Stride of 1024 float4 = 4096 floats = 83*49 + 29
#define QSTEP 83
#define RSTEP 29

__device__ __forceinline__ uint32_t smem_u32(const void* p) {
    return (uint32_t)__cvta_generic_to_shared(p);
}
__device__ __forceinline__ void bulk_load(uint32_t dst, const void* src,
                                          uint32_t bytes, uint32_t mbar) {
    asm volatile(
        "cp.async.bulk.shared::cta.global.mbarrier::complete_tx::bytes [%0], [%1], %2, [%3];"
        :: "r"(dst), "l"(src), "r"(bytes), "r"(mbar) : "memory");
}
__device__ __forceinline__ void mbar_expect_tx(uint32_t mbar, uint32_t bytes) {
    asm volatile("mbarrier.arrive.expect_tx.shared.b64 _, [%0], %1;"
                 :: "r"(mbar), "r"(bytes) : "memory");
}
__device__ __forceinline__ void mbar_wait(uint32_t mbar, uint32_t parity) {
    asm volatile(
        "{\n\t"
        ".reg .pred P;\n\t"
        "WAIT_LP_%=:\n\t"
        "mbarrier.try_wait.parity.acquire.cta.shared::cta.b64 P, [%0], %1, 0x989680;\n\t"
        "@P bra.uni WAIT_DN_%=;\n\t"
        "bra.uni WAIT_LP_%=;\n\t"
        "WAIT_DN_%=:\n\t"
        "}"
        :: "r"(mbar), "r"(parity) : "memory");
}

__global__ __launch_bounds__(NTHR, 1)
void gate_l2_kernel(const float* __restrict__ x, float* __restrict__ out, int N) {
    extern __shared__ float smem[];           // 2 * CHW floats
    float* const tiles[2] = { smem, smem + CHW };
    __shared__ float part[NTHR];
    __shared__ float gateS[CCH + 8];
    __shared__ float redA[32];
    __shared__ float redB[32];
    __shared__ __align__(8) unsigned long long mbar_store[2];

    const int tid  = threadIdx.x;
    const int lane = tid & 31;
    const int wid  = tid >> 5;
    const uint32_t mb[2] = { smem_u32(&mbar_store[0]), smem_u32(&mbar_store[1]) };

    if (tid == 0) {
        asm volatile("mbarrier.init.shared.b64 [%0], 1;" :: "r"(mb[0]) : "memory");
        asm volatile("mbarrier.init.shared.b64 [%0], 1;" :: "r"(mb[1]) : "memory");
    }
    __syncthreads();

    const int stride = gridDim.x;
    const int s0 = blockIdx.x;
    if (s0 >= N) return;

    // Prologue: preload samples s0 (buf 0) and s0+stride (buf 1).
    if (tid == 0) {
        mbar_expect_tx(mb[0], TILE_BYTES);
        bulk_load(smem_u32(tiles[0]), x + (size_t)s0 * CHW, TILE_BYTES, mb[0]);
        if (s0 + stride < N) {
            mbar_expect_tx(mb[1], TILE_BYTES);
            bulk_load(smem_u32(tiles[1]), x + (size_t)(s0 + stride) * CHW,
                      TILE_BYTES, mb[1]);
        }
    }

    uint32_t ph[2] = { 0u, 0u };
    int idx = 0;
    for (int s = s0; s < N; s += stride, idx++) {
        const int b = idx & 1;
        const float* tile = tiles[b];

        // Load of sample s was issued two iterations ago — ample slack.
        mbar_wait(mb[b], ph[b]);
        ph[b] ^= 1;

        // ---- Reduce from SMEM: per-channel sums, pair-split 25+24 ----
        {
            const int c    = tid & (CCH - 1);
            const int half = tid >> 9;
            const float* row = tile + c * HW + half * 25;
            float acc = 0.0f;
            #pragma unroll
            for (int j = 0; j < 24; j++) acc += row[j];
            if (half == 0) acc += row[24];
            part[tid] = acc;
        }
        __syncthreads();   // all tile reads done; part[] complete

        // Buffer b is now free: prefetch sample s + 2*stride into it.
        const int s2 = s + 2 * stride;
        if (s2 < N && tid == 0) {
            mbar_expect_tx(mb[b], TILE_BYTES);
            bulk_load(smem_u32(tiles[b]), x + (size_t)s2 * CHW, TILE_BYTES, mb[b]);
        }

        float y = 0.0f;
        if (tid < CCH) y = (part[tid] + part[tid + CCH]) * (1.0f / 49.0f);

        // ---- Stats: block reduce sum(y), sum(y^2) ----
        float a = y, bb = y * y;
        #pragma unroll
        for (int off = 16; off > 0; off >>= 1) {
            a  += __shfl_xor_sync(0xffffffffu, a, off);
            bb += __shfl_xor_sync(0xffffffffu, bb, off);
        }
        if (lane == 0) { redA[wid] = a; redB[wid] = bb; }
        __syncthreads();

        a  = redA[lane];
        bb = redB[lane];
        #pragma unroll
        for (int off = 16; off > 0; off >>= 1) {
            a  += __shfl_xor_sync(0xffffffffu, a, off);
            bb += __shfl_xor_sync(0xffffffffu, bb, off);
        }
        {
            const float m   = a  * (1.0f / (float)CCH);
            const float mx2 = bb * (1.0f / (float)CCH);
            float var = mx2 - m * m;
            var = var > 0.0f ? var : 0.0f;
            const float inv = rsqrtf(var + EPS);
            if (tid < CCH) {
                const float yn = (y - m) * inv;
                gateS[tid] = __expf(-yn * yn);    // C_PARAM=2 -> exp(-yn^2)
            }
        }
        __syncthreads();

        // ---- Apply: re-read x from L2 (lines just fetched by TMA),
        //      gate, posted STG out. No smem, no drains, no waits. ----
        {
            const float4* __restrict__ xg4 =
                reinterpret_cast<const float4*>(x + (size_t)s * CHW);
            float4* __restrict__ og4 =
                reinterpret_cast<float4*>(out + (size_t)s * CHW);
            int e = tid * 4;
            int q = e / HW;            // one divide per thread per sample
            int r = e - q * HW;
            #pragma unroll 2
            for (int i = tid; i < NVEC; i += NTHR) {
                float4 v = xg4[i];
                const float g0 = gateS[q];
                const float g1 = gateS[q + 1];
                v.x *= g0;
                v.y *= (r + 1 >= HW) ? g1 : g0;
                v.z *= (r + 2 >= HW) ? g1 : g0;
                v.w *= (r + 3 >= HW) ? g1 : g0;
                og4[i] = v;
                q += QSTEP; r += RSTEP;
                if (r >= HW) { r -= HW; q += 1; }
            }
        }
        // gateS/part reuse is ordered by next iteration's barriers.
    }
}

extern "C" void kernel_launch(void* const* d_in, const int* in_sizes, int n_in,
                              void* d_out, int out_size) {
    const float* x = (const float*)d_in[0];
    float* out = (float*)d_out;
    const int N = in_sizes[0] / CHW;   // 2048

    int sm_count = 0;
    if (cudaDeviceGetAttribute(&sm_count, cudaDevAttrMultiProcessorCount, 0)
        != cudaSuccess || sm_count <= 0)
        sm_count = 148;

    int grid = sm_count;               // 1 persistent CTA per SM
    if (grid > N) grid = N;

    const int dyn_smem = 2 * TILE_BYTES;   // 200,704 B
    cudaFuncSetAttribute(gate_l2_kernel,
                         cudaFuncAttributeMaxDynamicSharedMemorySize, dyn_smem);
    gate_l2_kernel<<<grid, NTHR, dyn_smem>>>(x, out, N);
}

// round 15
// speedup vs baseline: 1.2367x; 1.0605x over previous
#include <cuda_runtime.h>
#include <cstdint>

#define CCH    512
#define HW     49
#define CHW    (CCH * HW)         // 25088 floats per sample
#define HALF_F (CHW / 2)          // 12544 floats = 256 channels
#define NVEC2  (HALF_F / 4)       // 3136 float4 per half
#define NTHR   1024
#define EPS    1e-5f
#define TILE_BYTES (CHW * 4)      // 100352 B
#define HALF_BYTES (HALF_F * 4)   // 50176 B

// Apply stride: 1024 float4 = 4096 floats = 83*49 + 29
#define QSTEP 83
#define RSTEP 29

__device__ __forceinline__ uint32_t smem_u32(const void* p) {
    return (uint32_t)__cvta_generic_to_shared(p);
}
__device__ __forceinline__ void bulk_load(uint32_t dst, const void* src,
                                          uint32_t bytes, uint32_t mbar) {
    asm volatile(
        "cp.async.bulk.shared::cta.global.mbarrier::complete_tx::bytes [%0], [%1], %2, [%3];"
        :: "r"(dst), "l"(src), "r"(bytes), "r"(mbar) : "memory");
}
__device__ __forceinline__ void bulk_store(void* dst, uint32_t src, uint32_t bytes) {
    asm volatile(
        "cp.async.bulk.global.shared::cta.bulk_group [%0], [%1], %2;"
        :: "l"(dst), "r"(src), "r"(bytes) : "memory");
}
__device__ __forceinline__ void mbar_expect_tx(uint32_t mbar, uint32_t bytes) {
    asm volatile("mbarrier.arrive.expect_tx.shared.b64 _, [%0], %1;"
                 :: "r"(mbar), "r"(bytes) : "memory");
}
__device__ __forceinline__ void mbar_wait(uint32_t mbar, uint32_t parity) {
    asm volatile(
        "{\n\t"
        ".reg .pred P;\n\t"
        "WAIT_LP_%=:\n\t"
        "mbarrier.try_wait.parity.acquire.cta.shared::cta.b64 P, [%0], %1, 0x989680;\n\t"
        "@P bra.uni WAIT_DN_%=;\n\t"
        "bra.uni WAIT_LP_%=;\n\t"
        "WAIT_DN_%=:\n\t"
        "}"
        :: "r"(mbar), "r"(parity) : "memory");
}

__global__ __launch_bounds__(NTHR, 1)
void gate_hp_kernel(const float* __restrict__ x, float* __restrict__ out, int N) {
    extern __shared__ float smem[];        // 4 half-slots of HALF_F floats
    __shared__ float part[NTHR];
    __shared__ float gateS[CCH + 8];
    __shared__ float redA[32];
    __shared__ float redB[32];
    __shared__ __align__(8) unsigned long long mbar_store[2];

    const int tid  = threadIdx.x;
    const int lane = tid & 31;
    const int wid  = tid >> 5;
    const uint32_t mb[2] = { smem_u32(&mbar_store[0]), smem_u32(&mbar_store[1]) };

    if (tid == 0) {
        asm volatile("mbarrier.init.shared.b64 [%0], 1;" :: "r"(mb[0]) : "memory");
        asm volatile("mbarrier.init.shared.b64 [%0], 1;" :: "r"(mb[1]) : "memory");
    }
    __syncthreads();

    const int stride = gridDim.x;
    const int s0 = blockIdx.x;
    if (s0 >= N) return;

    // Slot base: buffer b (0/1), half h (0/1) -> smem + (2b+h)*HALF_F
    // Prologue: both halves of sample s0 into buffer 0.
    if (tid == 0) {
        mbar_expect_tx(mb[0], TILE_BYTES);
        const float* src = x + (size_t)s0 * CHW;
        bulk_load(smem_u32(smem),          src,          HALF_BYTES, mb[0]);
        bulk_load(smem_u32(smem + HALF_F), src + HALF_F, HALF_BYTES, mb[0]);
    }

    uint32_t ph[2] = { 0u, 0u };
    int idx = 0;
    for (int s = s0; s < N; s += stride, idx++) {
        const int b = idx & 1;
        float* const buf  = smem + (2 * b) * HALF_F;        // halves contiguous
        float* const nbuf = smem + (2 * (b ^ 1)) * HALF_F;
        const int sn = s + stride;
        const float* srcn = x + (size_t)sn * CHW;

        // Top: drain h1-store of idx-1 (committed mid prev iter, well aged),
        // keep h2-store of idx-1 outstanding; then load h1 of sample s+1.
        if (tid == 0) {
            asm volatile("cp.async.bulk.wait_group 1;" ::: "memory");
            if (sn < N) {
                mbar_expect_tx(mb[b ^ 1], TILE_BYTES);
                bulk_load(smem_u32(nbuf), srcn, HALF_BYTES, mb[b ^ 1]);
            }
        }

        // Wait for sample s (both halves; loads issued during prev iter).
        mbar_wait(mb[b], ph[b]);
        ph[b] ^= 1;

        // ---- Reduce: per-channel sums, pair-split 25+24 ----
        {
            const int c     = tid & (CCH - 1);
            const int split = tid >> 9;
            const float* row = buf + c * HW + split * 25;
            float acc = 0.0f;
            #pragma unroll
            for (int j = 0; j < 24; j++) acc += row[j];
            if (split == 0) acc += row[24];
            part[tid] = acc;
        }
        __syncthreads();

        float y = 0.0f;
        if (tid < CCH) y = (part[tid] + part[tid + CCH]) * (1.0f / 49.0f);

        float a = y, bb = y * y;
        #pragma unroll
        for (int off = 16; off > 0; off >>= 1) {
            a  += __shfl_xor_sync(0xffffffffu, a, off);
            bb += __shfl_xor_sync(0xffffffffu, bb, off);
        }
        if (lane == 0) { redA[wid] = a; redB[wid] = bb; }
        __syncthreads();

        a  = redA[lane];
        bb = redB[lane];
        #pragma unroll
        for (int off = 16; off > 0; off >>= 1) {
            a  += __shfl_xor_sync(0xffffffffu, a, off);
            bb += __shfl_xor_sync(0xffffffffu, bb, off);
        }
        {
            const float m   = a  * (1.0f / (float)CCH);
            const float mx2 = bb * (1.0f / (float)CCH);
            float var = mx2 - m * m;
            var = var > 0.0f ? var : 0.0f;
            const float inv = rsqrtf(var + EPS);
            if (tid < CCH) {
                const float yn = (y - m) * inv;
                gateS[tid] = __expf(-yn * yn);   // C_PARAM=2 -> exp(-yn^2)
            }
        }
        __syncthreads();

        // ---- Apply half 0 in place ----
        {
            float4* t4 = reinterpret_cast<float4*>(buf);
            int e = tid * 4;
            int q = e / HW;
            int r = e - q * HW;
            for (int i = tid; i < NVEC2; i += NTHR) {
                float4 v = t4[i];
                const float g0 = gateS[q];
                const float g1 = gateS[q + 1];
                v.x *= g0;
                v.y *= (r + 1 >= HW) ? g1 : g0;
                v.z *= (r + 2 >= HW) ? g1 : g0;
                v.w *= (r + 3 >= HW) ? g1 : g0;
                t4[i] = v;
                q += QSTEP; r += RSTEP;
                if (r >= HW) { r -= HW; q += 1; }
            }
        }
        __syncthreads();
        if (tid == 0) {
            asm volatile("fence.proxy.async.shared::cta;" ::: "memory");
            bulk_store(out + (size_t)s * CHW, smem_u32(buf), HALF_BYTES);
            asm volatile("cp.async.bulk.commit_group;" ::: "memory");
            // Drain h2-store of idx-1 (aged a full reduce+apply), keep the
            // h1-store just committed; then load h2 of sample s+1.
            asm volatile("cp.async.bulk.wait_group 1;" ::: "memory");
            if (sn < N)
                bulk_load(smem_u32(nbuf + HALF_F), srcn + HALF_F,
                          HALF_BYTES, mb[b ^ 1]);
        }

        // ---- Apply half 1 in place (gate channels 256..511) ----
        {
            float4* t4 = reinterpret_cast<float4*>(buf + HALF_F);
            int e = tid * 4;
            int q = e / HW;
            int r = e - q * HW;
            const float* gh = gateS + 256;
            for (int i = tid; i < NVEC2; i += NTHR) {
                float4 v = t4[i];
                const float g0 = gh[q];
                const float g1 = gh[q + 1];
                v.x *= g0;
                v.y *= (r + 1 >= HW) ? g1 : g0;
                v.z *= (r + 2 >= HW) ? g1 : g0;
                v.w *= (r + 3 >= HW) ? g1 : g0;
                t4[i] = v;
                q += QSTEP; r += RSTEP;
                if (r >= HW) { r -= HW; q += 1; }
            }
        }
        __syncthreads();
        if (tid == 0) {
            asm volatile("fence.proxy.async.shared::cta;" ::: "memory");
            bulk_store(out + (size_t)s * CHW + HALF_F,
                       smem_u32(buf + HALF_F), HALF_BYTES);
            asm volatile("cp.async.bulk.commit_group;" ::: "memory");
        }
    }

    if (tid == 0)
        asm volatile("cp.async.bulk.wait_group 0;" ::: "memory");
}

extern "C" void kernel_launch(void* const* d_in, const int* in_sizes, int n_in,
                              void* d_out, int out_size) {
    const float* x = (const float*)d_in[0];
    float* out = (float*)d_out;
    const int N = in_sizes[0] / CHW;   // 2048

    int sm_count = 0;
    if (cudaDeviceGetAttribute(&sm_count, cudaDevAttrMultiProcessorCount, 0)
        != cudaSuccess || sm_count <= 0)
        sm_count = 148;

    int grid = sm_count;               // 1 persistent CTA per SM
    if (grid > N) grid = N;

    const int dyn_smem = 2 * TILE_BYTES;   // 200,704 B (4 half-slots)
    cudaFuncSetAttribute(gate_hp_kernel,
                         cudaFuncAttributeMaxDynamicSharedMemorySize, dyn_smem);
    gate_hp_kernel<<<grid, NTHR, dyn_smem>>>(x, out, N);
}

// round 16
// speedup vs baseline: 1.6243x; 1.3134x over previous
#include <cuda_runtime.h>
#include <cstdint>

#define CCH    512
#define HW     49
#define CHW    (CCH * HW)         // 25088 floats per sample
#define NVEC   (CHW / 4)          // 6272 float4 per sample
#define NTHR   1024
#define EPS    1e-5f
#define NCHUNK 4
#define CHUNK_F     (CHW / NCHUNK)        // 6272 floats (128 channels)
#define CHUNK_BYTES (CHUNK_F * 4)         // 25088 B
#define TILE_BYTES  (CHW * 4)             // 100352 B

// Apply stride: 1024 float4 = 4096 floats = 83*49 + 29
#define QSTEP 83
#define RSTEP 29

__device__ __forceinline__ uint32_t smem_u32(const void* p) {
    return (uint32_t)__cvta_generic_to_shared(p);
}
__device__ __forceinline__ void bulk_load(uint32_t dst, const void* src,
                                          uint32_t bytes, uint32_t mbar) {
    asm volatile(
        "cp.async.bulk.shared::cta.global.mbarrier::complete_tx::bytes [%0], [%1], %2, [%3];"
        :: "r"(dst), "l"(src), "r"(bytes), "r"(mbar) : "memory");
}
__device__ __forceinline__ void mbar_expect_tx(uint32_t mbar, uint32_t bytes) {
    asm volatile("mbarrier.arrive.expect_tx.shared.b64 _, [%0], %1;"
                 :: "r"(mbar), "r"(bytes) : "memory");
}
__device__ __forceinline__ void mbar_wait(uint32_t mbar, uint32_t parity) {
    asm volatile(
        "{\n\t"
        ".reg .pred P;\n\t"
        "WAIT_LP_%=:\n\t"
        "mbarrier.try_wait.parity.acquire.cta.shared::cta.b64 P, [%0], %1, 0x989680;\n\t"
        "@P bra.uni WAIT_DN_%=;\n\t"
        "bra.uni WAIT_LP_%=;\n\t"
        "WAIT_DN_%=:\n\t"
        "}"
        :: "r"(mbar), "r"(parity) : "memory");
}

__global__ __launch_bounds__(NTHR, 1)
void gate_chunk_kernel(const float* __restrict__ x, float* __restrict__ out, int N) {
    extern __shared__ float smem[];        // 2 * CHW floats
    __shared__ float part[NTHR];
    __shared__ float gateS[CCH + 8];
    __shared__ float redA[32];
    __shared__ float redB[32];
    __shared__ __align__(8) unsigned long long mbar_store[2][NCHUNK];

    const int tid  = threadIdx.x;
    const int lane = tid & 31;
    const int wid  = tid >> 5;
    const int c    = tid & (CCH - 1);       // channel owned (pair-split)
    const int myck = c >> 7;                // this warp's chunk (uniform in warp)

    if (tid < 2 * NCHUNK) {
        asm volatile("mbarrier.init.shared.b64 [%0], 1;"
                     :: "r"(smem_u32(&mbar_store[tid >> 2][tid & 3])) : "memory");
    }
    __syncthreads();

    const int stride = gridDim.x;
    const int s0 = blockIdx.x;
    if (s0 >= N) return;

    float* const tiles[2] = { smem, smem + CHW };

    // Prologue: 4 chunk-loads of sample s0 into buffer 0.
    if (tid == 0) {
        const float* src = x + (size_t)s0 * CHW;
        #pragma unroll
        for (int k = 0; k < NCHUNK; k++) {
            const uint32_t m = smem_u32(&mbar_store[0][k]);
            mbar_expect_tx(m, CHUNK_BYTES);
            bulk_load(smem_u32(tiles[0]) + k * CHUNK_BYTES,
                      src + k * CHUNK_F, CHUNK_BYTES, m);
        }
    }

    uint32_t ph[2] = { 0u, 0u };
    int idx = 0;
    for (int s = s0; s < N; s += stride, idx++) {
        const int b = idx & 1;
        const float* tile = tiles[b];

        // Prefetch sample s+1 into the other buffer (4 chunks). Its previous
        // tenant was fully consumed before last iteration's trailing barrier.
        const int sn = s + stride;
        if (sn < N && tid == 0) {
            const float* srcn = x + (size_t)sn * CHW;
            #pragma unroll
            for (int k = 0; k < NCHUNK; k++) {
                const uint32_t m = smem_u32(&mbar_store[b ^ 1][k]);
                mbar_expect_tx(m, CHUNK_BYTES);
                bulk_load(smem_u32(tiles[b ^ 1]) + k * CHUNK_BYTES,
                          srcn + k * CHUNK_F, CHUNK_BYTES, m);
            }
        }

        // Each warp waits only for the chunk holding ITS channels — reduce
        // starts on first-arrived 25 KB instead of the full 100 KB.
        mbar_wait(smem_u32(&mbar_store[b][myck]), ph[b]);
        ph[b] ^= 1;

        // ---- Reduce: per-channel sums, pair-split 25+24 ----
        {
            const int split = tid >> 9;
            const float* row = tile + c * HW + split * 25;
            float acc = 0.0f;
            #pragma unroll
            for (int j = 0; j < 24; j++) acc += row[j];
            if (split == 0) acc += row[24];
            part[tid] = acc;
        }
        __syncthreads();   // also: every chunk had >=1 waiting warp -> whole
                           // tile is now resident for the apply phase.

        float y = 0.0f;
        if (tid < CCH) y = (part[tid] + part[tid + CCH]) * (1.0f / 49.0f);

        // ---- Stats: block reduce sum(y), sum(y^2) ----
        float a = y, bb = y * y;
        #pragma unroll
        for (int off = 16; off > 0; off >>= 1) {
            a  += __shfl_xor_sync(0xffffffffu, a, off);
            bb += __shfl_xor_sync(0xffffffffu, bb, off);
        }
        if (lane == 0) { redA[wid] = a; redB[wid] = bb; }
        __syncthreads();

        a  = redA[lane];
        bb = redB[lane];
        #pragma unroll
        for (int off = 16; off > 0; off >>= 1) {
            a  += __shfl_xor_sync(0xffffffffu, a, off);
            bb += __shfl_xor_sync(0xffffffffu, bb, off);
        }
        {
            const float m   = a  * (1.0f / (float)CCH);
            const float mx2 = bb * (1.0f / (float)CCH);
            float var = mx2 - m * m;
            var = var > 0.0f ? var : 0.0f;
            const float inv = rsqrtf(var + EPS);
            if (tid < CCH) {
                const float yn = (y - m) * inv;
                gateS[tid] = __expf(-yn * yn);   // C_PARAM=2 -> exp(-yn^2)
            }
        }
        __syncthreads();

        // ---- Apply: read tile from SMEM, gate, posted STG.128 out ----
        {
            const float4* tile4 = reinterpret_cast<const float4*>(tile);
            float4* __restrict__ og4 =
                reinterpret_cast<float4*>(out + (size_t)s * CHW);
            int e = tid * 4;
            int q = e / HW;            // one divide per thread per sample
            int r = e - q * HW;
            #pragma unroll 2
            for (int i = tid; i < NVEC; i += NTHR) {
                float4 v = tile4[i];
                const float g0 = gateS[q];
                const float g1 = gateS[q + 1];
                v.x *= g0;
                v.y *= (r + 1 >= HW) ? g1 : g0;
                v.z *= (r + 2 >= HW) ? g1 : g0;
                v.w *= (r + 3 >= HW) ? g1 : g0;
                og4[i] = v;
                q += QSTEP; r += RSTEP;
                if (r >= HW) { r -= HW; q += 1; }
            }
        }

        // All warps must finish reading this buffer before the next
        // iteration's prefetch overwrites the OTHER buffer's... (other
        // buffer is only written next iteration; THIS buffer is rewritten
        // in two iterations, after another trailing barrier). This barrier
        // protects buffer b^1: its apply reads (iter idx-1) are long done,
        // but gateS/part reuse next iteration needs all appliers done.
        __syncthreads();
    }
}

extern "C" void kernel_launch(void* const* d_in, const int* in_sizes, int n_in,
                              void* d_out, int out_size) {
    const float* x = (const float*)d_in[0];
    float* out = (float*)d_out;
    const int N = in_sizes[0] / CHW;   // 2048

    int sm_count = 0;
    if (cudaDeviceGetAttribute(&sm_count, cudaDevAttrMultiProcessorCount, 0)
        != cudaSuccess || sm_count <= 0)
        sm_count = 148;

    int grid = sm_count;               // 1 persistent CTA per SM
    if (grid > N) grid = N;

    const int dyn_smem = 2 * TILE_BYTES;   // 200,704 B
    cudaFuncSetAttribute(gate_chunk_kernel,
                         cudaFuncAttributeMaxDynamicSharedMemorySize, dyn_smem);
    gate_chunk_kernel<<<grid, NTHR, dyn_smem>>>(x, out, N);
}